// round 13
// baseline (speedup 1.0000x reference)
#include <cuda_runtime.h>
#include <cuda_bf16.h>
#include <cuda_fp16.h>
#include <cuda_fp8.h>
#include <stdint.h>

#define CDIM 256
#define HW_  9216
#define TT   32
#define VV   256
#define MTOT 8192
#define NB   64                       // 64 row-blocks of 128
#define PADB 272                      // 256B row + 16B pad: conflict-free, 16B-aligned
#define TILE_B (128 * PADB)           // 34816 bytes per fp8 tile buffer
#define HALF_B (64 * PADB)            // 17408: 64-row A tile (pos pass)
#define SMEM_NEG (4 * TILE_B)         // double-buffered (A,B) pairs = 136 KB
#define POS_SLOT (HALF_B + TILE_B)    // 52224
#define SMEM_POS (2 * POS_SLOT)       // 104448 -> 2 CTAs/SM
#define FSCALE 16.0f                  // feature scale (exact pow2); dot scales by 256
#define NPAIRS (NB * (NB + 1) / 2)    // 2080

__device__ __align__(256) uint8_t g_feats[(size_t)MTOT * CDIM];  // e4m3
__device__ float g_neg_sum[MTOT];
__device__ float g_pos_sum[MTOT];
__device__ float g_logns[MTOT];
__device__ float g_invns[MTOT];
__device__ int g_list_neg[NPAIRS];
__device__ int g_list_pos[2 * NPAIRS];
__device__ int g_cnt_neg, g_cnt_pos;
__device__ unsigned g_done_neg, g_done_pos;

// ---------------------------------------------------------------------------
// K1: gather + L2 normalize (single read pass, fp32) -> e4m3 feats (x16).
// Also zeroes accumulators and the completion counters (graph replay safe).
// ---------------------------------------------------------------------------
__global__ void __launch_bounds__(256) k_gather(
        const float* __restrict__ features,
        const int* __restrict__ batch_inds,
        const int* __restrict__ si32,
        float* __restrict__ out) {
    const int tid = threadIdx.x;
    const int t  = blockIdx.y;
    const int vq = blockIdx.x;
    const int vl = tid & 63;
    const int cg = tid >> 6;
    const int v  = vq * 64 + vl;

    if (blockIdx.x == 0 && blockIdx.y == 0 && tid == 0) {
        g_done_neg = 0u; g_done_pos = 0u;
    }
    int gz = ((blockIdx.y * 4 + blockIdx.x) << 8) + tid;
    if (gz < MTOT) { g_neg_sum[gz] = 0.f; g_pos_sum[gz] = 0.f; }

    // sample_inds may arrive as int64 or int32 (JAX x64 flag); sniff high words.
    bool is64 = (si32[1] == 0) && (si32[3] == 0) && (si32[5] == 0) && (si32[7] == 0);
    const int idx = t * VV + v;
    const int s = is64 ? (int)((const long long*)si32)[idx] : si32[idx];
    const int b = batch_inds[t];
    const float* base = features + (size_t)b * CDIM * HW_ + (size_t)cg * 64 * HW_ + s;

    float x[64];
#pragma unroll
    for (int i = 0; i < 64; i++) x[i] = __ldg(&base[(size_t)i * HW_]);
    float partial = 0.f;
#pragma unroll
    for (int i = 0; i < 64; i++) partial += x[i] * x[i];

    __shared__ float red[4][64];
    __shared__ float s_inv[64];
    red[cg][vl] = partial;
    __syncthreads();
    if (cg == 0) {
        float ss = red[0][vl] + red[1][vl] + red[2][vl] + red[3][vl];
        s_inv[vl] = 1.0f / fmaxf(sqrtf(ss), 1e-12f);
    }
    __syncthreads();
    const float inv = s_inv[vl] * FSCALE;

    uint32_t w[16];
#pragma unroll
    for (int i = 0; i < 16; i++) {
        __nv_fp8x2_storage_t p0 = __nv_cvt_float2_to_fp8x2(
            make_float2(x[4 * i] * inv, x[4 * i + 1] * inv), __NV_SATFINITE, __NV_E4M3);
        __nv_fp8x2_storage_t p1 = __nv_cvt_float2_to_fp8x2(
            make_float2(x[4 * i + 2] * inv, x[4 * i + 3] * inv), __NV_SATFINITE, __NV_E4M3);
        w[i] = (uint32_t)p0 | ((uint32_t)p1 << 16);
    }
    uint4* dst = (uint4*)(g_feats + (size_t)(t * VV + v) * CDIM + cg * 64);
    dst[0] = make_uint4(w[0], w[1], w[2], w[3]);
    dst[1] = make_uint4(w[4], w[5], w[6], w[7]);
    dst[2] = make_uint4(w[8], w[9], w[10], w[11]);
    dst[3] = make_uint4(w[12], w[13], w[14], w[15]);
}

// ---------------------------------------------------------------------------
// K2: symmetric block-pair worklists (I<=J). neg: full tiles. pos: two
// 64-row half-tiles per pair (bit 16 = half) for load balance.
// ---------------------------------------------------------------------------
__global__ void k_lists(const int* __restrict__ labels) {
    __shared__ int cN[NB], cP[NB];
    const int I = threadIdx.x;                   // 64 threads
    const int lI = labels[I >> 1];
    int nN = 0, nP = 0;
    for (int J = I; J < NB; J++) {
        if (labels[J >> 1] == lI) nP++; else nN++;
    }
    cN[I] = nN; cP[I] = nP;
    __syncthreads();
    int oN = 0, oP = 0;
    for (int k = 0; k < I; k++) { oN += cN[k]; oP += cP[k]; }
    for (int J = I; J < NB; J++) {
        int ent = (I << 8) | J;
        if (labels[J >> 1] == lI) {
            g_list_pos[2 * oP]     = ent;
            g_list_pos[2 * oP + 1] = ent | (1 << 16);
            oP++;
        } else g_list_neg[oN++] = ent;
    }
    if (I == NB - 1) { g_cnt_neg = oN; g_cnt_pos = 2 * oP; }
}

// ---------------------------------------------------------------------------
// mma.sync m16n8k32 e4m3 (A row-major, B col-major i.e. [n][k] storage)
// ---------------------------------------------------------------------------
__device__ __forceinline__ void mma_fp8(float c[4], const uint32_t a[4],
                                        const uint32_t b[2]) {
    asm volatile(
        "mma.sync.aligned.m16n8k32.row.col.f32.e4m3.e4m3.f32 "
        "{%0,%1,%2,%3}, {%4,%5,%6,%7}, {%8,%9}, {%0,%1,%2,%3};\n"
        : "+f"(c[0]), "+f"(c[1]), "+f"(c[2]), "+f"(c[3])
        : "r"(a[0]), "r"(a[1]), "r"(a[2]), "r"(a[3]), "r"(b[0]), "r"(b[1]));
}

__device__ __forceinline__ void cp16(uint32_t smem_dst, const void* gsrc) {
    asm volatile("cp.async.cg.shared.global [%0], [%1], 16;\n"
                 :: "r"(smem_dst), "l"(gsrc));
}
// 128x256 e4m3 tile: 8 cp.async/thread
__device__ __forceinline__ void load_tile(uint32_t dst, int row0, int tid) {
    const uint4* src = (const uint4*)g_feats + (size_t)row0 * (CDIM / 16);
#pragma unroll
    for (int it = 0; it < 8; it++) {
        int i = it * 256 + tid;
        int r = i >> 4, cb = i & 15;
        cp16(dst + r * PADB + cb * 16, src + r * 16 + cb);
    }
}
// 64x256 e4m3 half tile: 4 cp.async/thread
__device__ __forceinline__ void load_half(uint32_t dst, int row0, int tid) {
    const uint4* src = (const uint4*)g_feats + (size_t)row0 * (CDIM / 16);
#pragma unroll
    for (int it = 0; it < 4; it++) {
        int i = it * 256 + tid;
        int r = i >> 4, cb = i & 15;
        cp16(dst + r * PADB + cb * 16, src + r * 16 + cb);
    }
}

#define CWAIT1() asm volatile("cp.async.wait_group 1;\n")
#define CCOMMIT() asm volatile("cp.async.commit_group;\n")

// ---------------------------------------------------------------------------
// K3: NEG pass (measured-best R9 structure, untouched loop). Tail: last CTA
// (threadfence + counter) computes per-row log(ns), 1/ns for the pos pass.
// ---------------------------------------------------------------------------
__global__ void __launch_bounds__(256) k_neg() {
    extern __shared__ uint8_t smem[];
    const int cnt = g_cnt_neg;
    const int G = gridDim.x;
    const int tid = threadIdx.x;

    if ((int)blockIdx.x < cnt) {
        const int lane = tid & 31, warp = tid >> 5;
        const int wm = warp >> 1, wn = warp & 1;     // 4(m) x 2(n) warps
        const int g = lane >> 2, tig = lane & 3;

        uint32_t sbase;
        asm("{ .reg .u64 t; cvta.to.shared.u64 t, %1; cvt.u32.u64 %0, t; }"
            : "=r"(sbase) : "l"((void*)smem));

        {
            int ent = g_list_neg[blockIdx.x];
            load_tile(sbase, (ent >> 8) * 128, tid);
            load_tile(sbase + TILE_B, (ent & 255) * 128, tid);
        }
        CCOMMIT();
        if ((int)blockIdx.x + G < cnt) {
            int ent = g_list_neg[blockIdx.x + G];
            load_tile(sbase + 2 * TILE_B, (ent >> 8) * 128, tid);
            load_tile(sbase + 3 * TILE_B, (ent & 255) * 128, tid);
        }
        CCOMMIT();

        const float C2A = 0.011270273756944245f;  // 2/TEMP*log2(e)/256
        const float C2B = 2.8853900817779268f;    // 2/TEMP*log2(e)

        int s = 0;
        for (int p = blockIdx.x; p < cnt; p += G, s ^= 1) {
            const int ent = g_list_neg[p];
            const int I = ent >> 8, J = ent & 255;

            CWAIT1();
            __syncthreads();

            const uint8_t* As = smem + s * 2 * TILE_B;
            const uint8_t* Bs = As + TILE_B;

            float acc[2][8][4];
#pragma unroll
            for (int mi = 0; mi < 2; mi++)
#pragma unroll
                for (int ni = 0; ni < 8; ni++)
#pragma unroll
                    for (int e = 0; e < 4; e++) acc[mi][ni][e] = 0.f;

#pragma unroll
            for (int kk = 0; kk < CDIM; kk += 32) {
                uint32_t a[2][4], b[8][2];
#pragma unroll
                for (int mi = 0; mi < 2; mi++) {
                    const uint8_t* ap = &As[(wm * 32 + mi * 16 + g) * PADB + kk + tig * 4];
                    a[mi][0] = *(const uint32_t*)ap;
                    a[mi][1] = *(const uint32_t*)(ap + 8 * PADB);
                    a[mi][2] = *(const uint32_t*)(ap + 16);
                    a[mi][3] = *(const uint32_t*)(ap + 8 * PADB + 16);
                }
#pragma unroll
                for (int ni = 0; ni < 8; ni++) {
                    const uint8_t* bp = &Bs[(wn * 64 + ni * 8 + g) * PADB + kk + tig * 4];
                    b[ni][0] = *(const uint32_t*)bp;
                    b[ni][1] = *(const uint32_t*)(bp + 16);
                }
#pragma unroll
                for (int mi = 0; mi < 2; mi++)
#pragma unroll
                    for (int ni = 0; ni < 8; ni++)
                        mma_fp8(acc[mi][ni], a[mi], b[ni]);
            }

            // epilogue: exp + scatter rows (I) and cols (J)
            float colp[16];
#pragma unroll
            for (int k = 0; k < 16; k++) colp[k] = 0.f;

#pragma unroll
            for (int mi = 0; mi < 2; mi++) {
#pragma unroll
                for (int h = 0; h < 2; h++) {
                    float rsum = 0.f;
#pragma unroll
                    for (int ni = 0; ni < 8; ni++) {
                        float x0 = fmaf(acc[mi][ni][h * 2 + 0], C2A, -C2B);
                        float x1 = fmaf(acc[mi][ni][h * 2 + 1], C2A, -C2B);
                        __half2 hx = __floats2half2_rn(x0, x1);
                        uint32_t xu = *reinterpret_cast<uint32_t*>(&hx), eu;
                        asm("ex2.approx.f16x2 %0, %1;" : "=r"(eu) : "r"(xu));
                        __half2 he = *reinterpret_cast<__half2*>(&eu);
                        float2 fe = __half22float2(he);
                        rsum += fe.x + fe.y;
                        colp[ni * 2 + 0] += fe.x;
                        colp[ni * 2 + 1] += fe.y;
                    }
                    rsum += __shfl_xor_sync(0xffffffffu, rsum, 1);
                    rsum += __shfl_xor_sync(0xffffffffu, rsum, 2);
                    if (tig == 0) {
                        int gi = I * 128 + wm * 32 + mi * 16 + h * 8 + g;
                        atomicAdd(&g_neg_sum[gi], rsum);
                    }
                }
            }
#pragma unroll
            for (int k = 0; k < 16; k++) {
                float v = colp[k];
                v += __shfl_xor_sync(0xffffffffu, v, 4);
                v += __shfl_xor_sync(0xffffffffu, v, 8);
                v += __shfl_xor_sync(0xffffffffu, v, 16);
                if (lane < 4) {
                    int gj = J * 128 + wn * 64 + (k >> 1) * 8 + lane * 2 + (k & 1);
                    atomicAdd(&g_neg_sum[gj], v);
                }
            }

            __syncthreads();                         // done reading slot s
            if (p + 2 * G < cnt) {                   // prefetch pair p+2G into slot s
                int en = g_list_neg[p + 2 * G];
                load_tile(sbase + s * 2 * TILE_B, (en >> 8) * 128, tid);
                load_tile(sbase + s * 2 * TILE_B + TILE_B, (en & 255) * 128, tid);
            }
            CCOMMIT();
        }
    }

    // ---- tail: last CTA computes log(ns), 1/ns for every row ----
    __threadfence();
    __shared__ unsigned s_rank;
    if (tid == 0) s_rank = atomicAdd(&g_done_neg, 1u);
    __syncthreads();
    if (s_rank == (unsigned)(gridDim.x - 1)) {
#pragma unroll
        for (int it = 0; it < MTOT / 256; it++) {
            int i = it * 256 + tid;
            float ns = fmaxf(__ldcg(&g_neg_sum[i]), 1e-30f);
            g_logns[i] = __logf(ns);
            g_invns[i] = __fdividef(1.0f, ns);
        }
    }
}

// ---------------------------------------------------------------------------
// K4: POS pass, 64x128 half-tiles (2 CTAs/SM). Per element:
//   log(e^l + ns) = log ns + log1p(e^l/ns),  log1p(p) ~= p - p^2/2
// log ns / 1/ns are PRELOADED from k_neg's tail (no MUFU chains here).
// Tail: last CTA computes the final loss (replaces k_final launch).
// ---------------------------------------------------------------------------
__global__ void __launch_bounds__(256) k_pos(const int* __restrict__ labels,
                                             float* __restrict__ out) {
    extern __shared__ uint8_t smem[];
    const int cnt = g_cnt_pos;
    const int G = gridDim.x;
    const int tid = threadIdx.x;

    if ((int)blockIdx.x < cnt) {
        const int lane = tid & 31, warp = tid >> 5;
        const int wm = warp >> 1, wn = warp & 1;     // 4(m over 64 rows) x 2(n)
        const int g = lane >> 2, tig = lane & 3;

        uint32_t sbase;
        asm("{ .reg .u64 t; cvta.to.shared.u64 t, %1; cvt.u32.u64 %0, t; }"
            : "=r"(sbase) : "l"((void*)smem));

        {
            int ent = g_list_pos[blockIdx.x];
            load_half(sbase, ((ent >> 8) & 255) * 128 + (ent >> 16) * 64, tid);
            load_tile(sbase + HALF_B, (ent & 255) * 128, tid);
        }
        CCOMMIT();
        if ((int)blockIdx.x + G < cnt) {
            int ent = g_list_pos[blockIdx.x + G];
            load_half(sbase + POS_SLOT, ((ent >> 8) & 255) * 128 + (ent >> 16) * 64, tid);
            load_tile(sbase + POS_SLOT + HALF_B, (ent & 255) * 128, tid);
        }
        CCOMMIT();

        const float RSC = 0.0078125f;                 // 1/128: l = draw/128 - 2

        int s = 0;
        for (int p = blockIdx.x; p < cnt; p += G, s ^= 1) {
            const int ent = g_list_pos[p];
            const int I = (ent >> 8) & 255, J = ent & 255, half = ent >> 16;
            const int rowA = I * 128 + half * 64;
            const bool diag = (I == J);

            CWAIT1();
            __syncthreads();

            const uint8_t* As = smem + s * POS_SLOT;
            const uint8_t* Bs = As + HALF_B;

            float acc[8][4];
#pragma unroll
            for (int ni = 0; ni < 8; ni++)
#pragma unroll
                for (int e = 0; e < 4; e++) acc[ni][e] = 0.f;

#pragma unroll
            for (int kk = 0; kk < CDIM; kk += 32) {
                uint32_t a[4], b[8][2];
                const uint8_t* ap = &As[(wm * 16 + g) * PADB + kk + tig * 4];
                a[0] = *(const uint32_t*)ap;
                a[1] = *(const uint32_t*)(ap + 8 * PADB);
                a[2] = *(const uint32_t*)(ap + 16);
                a[3] = *(const uint32_t*)(ap + 8 * PADB + 16);
#pragma unroll
                for (int ni = 0; ni < 8; ni++) {
                    const uint8_t* bp = &Bs[(wn * 64 + ni * 8 + g) * PADB + kk + tig * 4];
                    b[ni][0] = *(const uint32_t*)bp;
                    b[ni][1] = *(const uint32_t*)(bp + 16);
                }
#pragma unroll
                for (int ni = 0; ni < 8; ni++)
                    mma_fp8(acc[ni], a, b[ni]);
            }

            __syncthreads();                          // smem slot s free
            if (p + 2 * G < cnt) {                    // prefetch (hidden by epilogue)
                int en = g_list_pos[p + 2 * G];
                load_half(sbase + s * POS_SLOT,
                          ((en >> 8) & 255) * 128 + (en >> 16) * 64, tid);
                load_tile(sbase + s * POS_SLOT + HALF_B, (en & 255) * 128, tid);
            }
            CCOMMIT();

            // per-column log ns / 1/ns: preloaded (2 L2-hot loads per col)
            float logc[16], invc[16], colp[16];
#pragma unroll
            for (int k = 0; k < 16; k++) {
                int gj = J * 128 + wn * 64 + (k >> 1) * 8 + tig * 2 + (k & 1);
                logc[k] = __ldg(&g_logns[gj]);
                invc[k] = __ldg(&g_invns[gj]);
                colp[k] = 0.f;
            }

#pragma unroll
            for (int h = 0; h < 2; h++) {
                const int gi = rowA + wm * 16 + h * 8 + g;
                const float logr = __ldg(&g_logns[gi]);
                const float invr = __ldg(&g_invns[gi]);
                float rsum = 0.f;
#pragma unroll
                for (int ni = 0; ni < 8; ni++) {
#pragma unroll
                    for (int e = 0; e < 2; e++) {
                        const int k = ni * 2 + e;
                        float draw = acc[ni][h * 2 + e];
                        float l = fmaf(draw, RSC, -2.0f);
                        float el = __expf(l);         // ex2 + mul
                        if (!diag) {
                            float q = el * invc[k];
                            colp[k] += (l - logc[k]) - q * fmaf(q, -0.5f, 1.0f);
                        }
                        int gj = J * 128 + wn * 64 + ni * 8 + tig * 2 + e;
                        if (!diag || gi != gj) {
                            float pr = el * invr;
                            rsum += (l - logr) - pr * fmaf(pr, -0.5f, 1.0f);
                        }
                    }
                }
                rsum += __shfl_xor_sync(0xffffffffu, rsum, 1);
                rsum += __shfl_xor_sync(0xffffffffu, rsum, 2);
                if (tig == 0) atomicAdd(&g_pos_sum[gi], rsum);
            }

            if (!diag) {
#pragma unroll
                for (int k = 0; k < 16; k++) {
                    float v = colp[k];
                    v += __shfl_xor_sync(0xffffffffu, v, 4);
                    v += __shfl_xor_sync(0xffffffffu, v, 8);
                    v += __shfl_xor_sync(0xffffffffu, v, 16);
                    if (lane < 4) {
                        int gj = J * 128 + wn * 64 + (k >> 1) * 8 + lane * 2 + (k & 1);
                        atomicAdd(&g_pos_sum[gj], v);
                    }
                }
            }
        }
    }

    // ---- tail: last CTA computes the final loss ----
    __threadfence();
    __shared__ unsigned s_rank;
    if (tid == 0) s_rank = atomicAdd(&g_done_pos, 1u);
    __syncthreads();
    if (s_rank == (unsigned)(gridDim.x - 1)) {
        __shared__ float rcnt[TT];
        __shared__ float wred[8];
        if (tid < TT) {
            int ml = labels[tid], c = 0;
            for (int u = 0; u < TT; u++) c += (labels[u] == ml) ? 1 : 0;
            rcnt[tid] = 1.0f / (float)(c * VV - 1);   // always >= 255 > EPS
        }
        __syncthreads();
        float sacc = 0.f;
#pragma unroll
        for (int it = 0; it < MTOT / 256; it++) {
            int i = it * 256 + tid;
            sacc += __ldcg(&g_pos_sum[i]) * rcnt[i >> 8];
        }
#pragma unroll
        for (int off = 16; off > 0; off >>= 1)
            sacc += __shfl_xor_sync(0xffffffffu, sacc, off);
        if ((tid & 31) == 0) wred[tid >> 5] = sacc;
        __syncthreads();
        if (tid == 0) {
            float tot = 0.f;
#pragma unroll
            for (int w = 0; w < 8; w++) tot += wred[w];
            out[0] = -tot * (1.0f / (float)MTOT);
        }
    }
}

// ---------------------------------------------------------------------------
extern "C" void kernel_launch(void* const* d_in, const int* in_sizes, int n_in,
                              void* d_out, int out_size) {
    const float* features   = (const float*)d_in[0];
    const int*   batch_inds = (const int*)d_in[1];
    const int*   si32       = (const int*)d_in[2];  // int32 or int64 (sniffed)
    const int*   labels     = (const int*)d_in[3];
    float*       out        = (float*)d_out;

    cudaFuncSetAttribute(k_neg, cudaFuncAttributeMaxDynamicSharedMemorySize, SMEM_NEG);
    cudaFuncSetAttribute(k_pos, cudaFuncAttributeMaxDynamicSharedMemorySize, SMEM_POS);

    k_gather<<<dim3(4, TT), 256>>>(features, batch_inds, si32, out);
    k_lists<<<1, NB>>>(labels);
    k_neg<<<152, 256, SMEM_NEG>>>();
    k_pos<<<304, 256, SMEM_POS>>>(labels, out);
}

// round 15
// speedup vs baseline: 1.2136x; 1.2136x over previous
#include <cuda_runtime.h>
#include <cuda_bf16.h>
#include <cuda_fp16.h>
#include <cuda_fp8.h>
#include <stdint.h>

#define CDIM 256
#define HW_  9216
#define TT   32
#define VV   256
#define MTOT 8192
#define NB   64                       // 64 row-blocks of 128
#define PADB 272                      // 256B row + 16B pad: conflict-free, 16B-aligned
#define TILE_B (128 * PADB)           // 34816 bytes per fp8 tile buffer
#define SMEM_MAIN (4 * TILE_B)        // double-buffered (A,B) pairs = 136 KB
#define FSCALE 16.0f                  // feature scale (exact pow2); dot scales by 256
#define NPAIRS (NB * (NB + 1) / 2)    // 2080

__device__ __align__(256) uint8_t g_feats[(size_t)MTOT * CDIM];  // e4m3
__device__ float g_neg_sum[MTOT];
__device__ float g_pos_sum[MTOT];
__device__ int g_list_neg[NPAIRS];
__device__ int g_list_pos[NPAIRS];
__device__ int g_cnt_neg, g_cnt_pos;

// ---------------------------------------------------------------------------
// K1: gather + L2 normalize (single read pass, fp32) -> e4m3 feats (x16).
// CTA(0,0) additionally builds the symmetric block-pair worklists (labels
// are an input, so no cross-CTA ordering is needed; done under DRAM latency).
// ---------------------------------------------------------------------------
__global__ void __launch_bounds__(256) k_gather(
        const float* __restrict__ features,
        const int* __restrict__ batch_inds,
        const int* __restrict__ si32,
        const int* __restrict__ labels,
        float* __restrict__ out) {
    const int tid = threadIdx.x;
    const int t  = blockIdx.y;
    const int vq = blockIdx.x;
    const int vl = tid & 63;
    const int cg = tid >> 6;
    const int v  = vq * 64 + vl;

    // ---- CTA(0,0): worklists (uniform branch; inner syncs are CTA-local) ----
    if (blockIdx.x == 0 && blockIdx.y == 0) {
        __shared__ int cN[NB], cP[NB];
        if (tid == 0) out[0] = 0.f;
        if (tid < NB) {
            const int lI = labels[tid >> 1];
            int nN = 0, nP = 0;
            for (int J = tid; J < NB; J++) {
                if (labels[J >> 1] == lI) nP++; else nN++;
            }
            cN[tid] = nN; cP[tid] = nP;
        }
        __syncthreads();
        if (tid < NB) {
            const int lI = labels[tid >> 1];
            int oN = 0, oP = 0;
            for (int k = 0; k < tid; k++) { oN += cN[k]; oP += cP[k]; }
            for (int J = tid; J < NB; J++) {
                int ent = (tid << 8) | J;
                if (labels[J >> 1] == lI) g_list_pos[oP++] = ent;
                else                      g_list_neg[oN++] = ent;
            }
            if (tid == NB - 1) { g_cnt_neg = oN; g_cnt_pos = oP; }
        }
        __syncthreads();
    }

    int gz = ((blockIdx.y * 4 + blockIdx.x) << 8) + tid;
    if (gz < MTOT) { g_neg_sum[gz] = 0.f; g_pos_sum[gz] = 0.f; }

    // sample_inds may arrive as int64 or int32 (JAX x64 flag); sniff high words.
    bool is64 = (si32[1] == 0) && (si32[3] == 0) && (si32[5] == 0) && (si32[7] == 0);
    const int idx = t * VV + v;
    const int s = is64 ? (int)((const long long*)si32)[idx] : si32[idx];
    const int b = batch_inds[t];
    const float* base = features + (size_t)b * CDIM * HW_ + (size_t)cg * 64 * HW_ + s;

    float x[64];
#pragma unroll
    for (int i = 0; i < 64; i++) x[i] = __ldg(&base[(size_t)i * HW_]);
    float partial = 0.f;
#pragma unroll
    for (int i = 0; i < 64; i++) partial += x[i] * x[i];

    __shared__ float red[4][64];
    __shared__ float s_inv[64];
    red[cg][vl] = partial;
    __syncthreads();
    if (cg == 0) {
        float ss = red[0][vl] + red[1][vl] + red[2][vl] + red[3][vl];
        s_inv[vl] = 1.0f / fmaxf(sqrtf(ss), 1e-12f);
    }
    __syncthreads();
    const float inv = s_inv[vl] * FSCALE;

    uint32_t w[16];
#pragma unroll
    for (int i = 0; i < 16; i++) {
        __nv_fp8x2_storage_t p0 = __nv_cvt_float2_to_fp8x2(
            make_float2(x[4 * i] * inv, x[4 * i + 1] * inv), __NV_SATFINITE, __NV_E4M3);
        __nv_fp8x2_storage_t p1 = __nv_cvt_float2_to_fp8x2(
            make_float2(x[4 * i + 2] * inv, x[4 * i + 3] * inv), __NV_SATFINITE, __NV_E4M3);
        w[i] = (uint32_t)p0 | ((uint32_t)p1 << 16);
    }
    uint4* dst = (uint4*)(g_feats + (size_t)(t * VV + v) * CDIM + cg * 64);
    dst[0] = make_uint4(w[0], w[1], w[2], w[3]);
    dst[1] = make_uint4(w[4], w[5], w[6], w[7]);
    dst[2] = make_uint4(w[8], w[9], w[10], w[11]);
    dst[3] = make_uint4(w[12], w[13], w[14], w[15]);
}

// ---------------------------------------------------------------------------
// mma.sync m16n8k32 e4m3 (A row-major, B col-major i.e. [n][k] storage)
// ---------------------------------------------------------------------------
__device__ __forceinline__ void mma_fp8(float c[4], const uint32_t a[4],
                                        const uint32_t b[2]) {
    asm volatile(
        "mma.sync.aligned.m16n8k32.row.col.f32.e4m3.e4m3.f32 "
        "{%0,%1,%2,%3}, {%4,%5,%6,%7}, {%8,%9}, {%0,%1,%2,%3};\n"
        : "+f"(c[0]), "+f"(c[1]), "+f"(c[2]), "+f"(c[3])
        : "r"(a[0]), "r"(a[1]), "r"(a[2]), "r"(a[3]), "r"(b[0]), "r"(b[1]));
}

__device__ __forceinline__ void cp16(uint32_t smem_dst, const void* gsrc) {
    asm volatile("cp.async.cg.shared.global [%0], [%1], 16;\n"
                 :: "r"(smem_dst), "l"(gsrc));
}
// 128x256 e4m3 tile: 8 cp.async/thread
__device__ __forceinline__ void load_tile(uint32_t dst, int row0, int tid) {
    const uint4* src = (const uint4*)g_feats + (size_t)row0 * (CDIM / 16);
#pragma unroll
    for (int it = 0; it < 8; it++) {
        int i = it * 256 + tid;
        int r = i >> 4, cb = i & 15;
        cp16(dst + r * PADB + cb * 16, src + r * 16 + cb);
    }
}

#define CWAIT1() asm volatile("cp.async.wait_group 1;\n")
#define CCOMMIT() asm volatile("cp.async.commit_group;\n")

// ---------------------------------------------------------------------------
// K2: NEG pass (exact measured-best R9 structure, unchanged).
// neg_sum[i] += exp(2cos-2) scattered to I-rows and J-cols per tile pair.
// Raw MMA output = 256*cos (features carry x16); m=2 stabilizer cancels.
// ---------------------------------------------------------------------------
__global__ void __launch_bounds__(256) k_neg() {
    extern __shared__ uint8_t smem[];
    const int cnt = g_cnt_neg;
    const int G = gridDim.x;
    if ((int)blockIdx.x >= cnt) return;

    const int tid = threadIdx.x;
    const int lane = tid & 31, warp = tid >> 5;
    const int wm = warp >> 1, wn = warp & 1;     // 4(m) x 2(n) warps
    const int g = lane >> 2, tig = lane & 3;

    uint32_t sbase;
    asm("{ .reg .u64 t; cvta.to.shared.u64 t, %1; cvt.u32.u64 %0, t; }"
        : "=r"(sbase) : "l"((void*)smem));

    {
        int ent = g_list_neg[blockIdx.x];
        load_tile(sbase, (ent >> 8) * 128, tid);
        load_tile(sbase + TILE_B, (ent & 255) * 128, tid);
    }
    CCOMMIT();
    if ((int)blockIdx.x + G < cnt) {
        int ent = g_list_neg[blockIdx.x + G];
        load_tile(sbase + 2 * TILE_B, (ent >> 8) * 128, tid);
        load_tile(sbase + 3 * TILE_B, (ent & 255) * 128, tid);
    }
    CCOMMIT();

    const float C2A = 0.011270273756944245f;  // 2/TEMP*log2(e)/256
    const float C2B = 2.8853900817779268f;    // 2/TEMP*log2(e)

    int s = 0;
    for (int p = blockIdx.x; p < cnt; p += G, s ^= 1) {
        const int ent = g_list_neg[p];
        const int I = ent >> 8, J = ent & 255;

        CWAIT1();
        __syncthreads();

        const uint8_t* As = smem + s * 2 * TILE_B;
        const uint8_t* Bs = As + TILE_B;

        float acc[2][8][4];
#pragma unroll
        for (int mi = 0; mi < 2; mi++)
#pragma unroll
            for (int ni = 0; ni < 8; ni++)
#pragma unroll
                for (int e = 0; e < 4; e++) acc[mi][ni][e] = 0.f;

#pragma unroll
        for (int kk = 0; kk < CDIM; kk += 32) {
            uint32_t a[2][4], b[8][2];
#pragma unroll
            for (int mi = 0; mi < 2; mi++) {
                const uint8_t* ap = &As[(wm * 32 + mi * 16 + g) * PADB + kk + tig * 4];
                a[mi][0] = *(const uint32_t*)ap;
                a[mi][1] = *(const uint32_t*)(ap + 8 * PADB);
                a[mi][2] = *(const uint32_t*)(ap + 16);
                a[mi][3] = *(const uint32_t*)(ap + 8 * PADB + 16);
            }
#pragma unroll
            for (int ni = 0; ni < 8; ni++) {
                const uint8_t* bp = &Bs[(wn * 64 + ni * 8 + g) * PADB + kk + tig * 4];
                b[ni][0] = *(const uint32_t*)bp;
                b[ni][1] = *(const uint32_t*)(bp + 16);
            }
#pragma unroll
            for (int mi = 0; mi < 2; mi++)
#pragma unroll
                for (int ni = 0; ni < 8; ni++)
                    mma_fp8(acc[mi][ni], a[mi], b[ni]);
        }

        // epilogue: exp + scatter rows (I) and cols (J)
        float colp[16];
#pragma unroll
        for (int k = 0; k < 16; k++) colp[k] = 0.f;

#pragma unroll
        for (int mi = 0; mi < 2; mi++) {
#pragma unroll
            for (int h = 0; h < 2; h++) {
                float rsum = 0.f;
#pragma unroll
                for (int ni = 0; ni < 8; ni++) {
                    float x0 = fmaf(acc[mi][ni][h * 2 + 0], C2A, -C2B);
                    float x1 = fmaf(acc[mi][ni][h * 2 + 1], C2A, -C2B);
                    __half2 hx = __floats2half2_rn(x0, x1);
                    uint32_t xu = *reinterpret_cast<uint32_t*>(&hx), eu;
                    asm("ex2.approx.f16x2 %0, %1;" : "=r"(eu) : "r"(xu));
                    __half2 he = *reinterpret_cast<__half2*>(&eu);
                    float2 fe = __half22float2(he);
                    rsum += fe.x + fe.y;
                    colp[ni * 2 + 0] += fe.x;
                    colp[ni * 2 + 1] += fe.y;
                }
                rsum += __shfl_xor_sync(0xffffffffu, rsum, 1);
                rsum += __shfl_xor_sync(0xffffffffu, rsum, 2);
                if (tig == 0) {
                    int gi = I * 128 + wm * 32 + mi * 16 + h * 8 + g;
                    atomicAdd(&g_neg_sum[gi], rsum);
                }
            }
        }
#pragma unroll
        for (int k = 0; k < 16; k++) {
            float v = colp[k];
            v += __shfl_xor_sync(0xffffffffu, v, 4);
            v += __shfl_xor_sync(0xffffffffu, v, 8);
            v += __shfl_xor_sync(0xffffffffu, v, 16);
            if (lane < 4) {
                int gj = J * 128 + wn * 64 + (k >> 1) * 8 + lane * 2 + (k & 1);
                atomicAdd(&g_neg_sum[gj], v);
            }
        }

        __syncthreads();                         // done reading slot s
        if (p + 2 * G < cnt) {                   // prefetch pair p+2G into slot s
            int en = g_list_neg[p + 2 * G];
            load_tile(sbase + s * 2 * TILE_B, (en >> 8) * 128, tid);
            load_tile(sbase + s * 2 * TILE_B + TILE_B, (en & 255) * 128, tid);
        }
        CCOMMIT();
    }
}

// ---------------------------------------------------------------------------
// K3: POS pass, R9 full-tile structure. Per tile, a 256-entry smem table of
// (log ns, 1/ns) is built (ONE __logf + __fdividef per thread per tile) so
// the per-element epilogue is 1 fp16x2-ex2 + FMAs:
//   log(e^l + ns) = log ns + log1p(e^l/ns),  log1p(p) ~= p - p^2/2
// (p <= 8e-3 -> approx error < 3e-7; fp16 el rel err 5e-4 scales by p -> ~4e-6)
// ---------------------------------------------------------------------------
__global__ void __launch_bounds__(256) k_pos() {
    extern __shared__ uint8_t smem[];
    __shared__ float slog[256], sinv[256];       // [0:128)=I rows, [128:256)=J rows
    const int cnt = g_cnt_pos;
    const int G = gridDim.x;
    if ((int)blockIdx.x >= cnt) return;

    const int tid = threadIdx.x;
    const int lane = tid & 31, warp = tid >> 5;
    const int wm = warp >> 1, wn = warp & 1;     // 4(m) x 2(n) warps
    const int g = lane >> 2, tig = lane & 3;

    uint32_t sbase;
    asm("{ .reg .u64 t; cvta.to.shared.u64 t, %1; cvt.u32.u64 %0, t; }"
        : "=r"(sbase) : "l"((void*)smem));

    {
        int ent = g_list_pos[blockIdx.x];
        load_tile(sbase, (ent >> 8) * 128, tid);
        load_tile(sbase + TILE_B, (ent & 255) * 128, tid);
    }
    CCOMMIT();
    if ((int)blockIdx.x + G < cnt) {
        int ent = g_list_pos[blockIdx.x + G];
        load_tile(sbase + 2 * TILE_B, (ent >> 8) * 128, tid);
        load_tile(sbase + 3 * TILE_B, (ent & 255) * 128, tid);
    }
    CCOMMIT();

    const float C2A = 0.011270273756944245f;  // 2/TEMP*log2(e)/256
    const float C2B = 2.8853900817779268f;    // 2/TEMP*log2(e)
    const float RSC = 0.0078125f;             // 1/128: l = draw/128 - 2

    int s = 0;
    for (int p = blockIdx.x; p < cnt; p += G, s ^= 1) {
        const int ent = g_list_pos[p];
        const int I = ent >> 8, J = ent & 255;
        const bool diag = (I == J);

        CWAIT1();
        __syncthreads();

        const uint8_t* As = smem + s * 2 * TILE_B;
        const uint8_t* Bs = As + TILE_B;

        float acc[2][8][4];
#pragma unroll
        for (int mi = 0; mi < 2; mi++)
#pragma unroll
            for (int ni = 0; ni < 8; ni++)
#pragma unroll
                for (int e = 0; e < 4; e++) acc[mi][ni][e] = 0.f;

#pragma unroll
        for (int kk = 0; kk < CDIM; kk += 32) {
            uint32_t a[2][4], b[8][2];
#pragma unroll
            for (int mi = 0; mi < 2; mi++) {
                const uint8_t* ap = &As[(wm * 32 + mi * 16 + g) * PADB + kk + tig * 4];
                a[mi][0] = *(const uint32_t*)ap;
                a[mi][1] = *(const uint32_t*)(ap + 8 * PADB);
                a[mi][2] = *(const uint32_t*)(ap + 16);
                a[mi][3] = *(const uint32_t*)(ap + 8 * PADB + 16);
            }
#pragma unroll
            for (int ni = 0; ni < 8; ni++) {
                const uint8_t* bp = &Bs[(wn * 64 + ni * 8 + g) * PADB + kk + tig * 4];
                b[ni][0] = *(const uint32_t*)bp;
                b[ni][1] = *(const uint32_t*)(bp + 16);
            }
#pragma unroll
            for (int mi = 0; mi < 2; mi++)
#pragma unroll
                for (int ni = 0; ni < 8; ni++)
                    mma_fp8(acc[mi][ni], a[mi], b[ni]);
        }

        __syncthreads();                         // smem tile slot s free
        if (p + 2 * G < cnt) {                   // prefetch pair p+2G into slot s
            int en = g_list_pos[p + 2 * G];
            load_tile(sbase + s * 2 * TILE_B, (en >> 8) * 128, tid);
            load_tile(sbase + s * 2 * TILE_B + TILE_B, (en & 255) * 128, tid);
        }
        CCOMMIT();

        // ---- per-tile table: log ns, 1/ns for the 256 rows involved ----
        {
            int r = (tid < 128) ? (I * 128 + tid) : (J * 128 + (tid - 128));
            float ns = g_neg_sum[r];
            slog[tid] = __logf(ns);
            sinv[tid] = __fdividef(1.0f, ns);
        }
        __syncthreads();

        // hoist the 16 column constants for this thread
        float logc[16], invc[16], colp[16];
#pragma unroll
        for (int k = 0; k < 16; k++) {
            int lj = wn * 64 + (k >> 1) * 8 + tig * 2 + (k & 1);
            logc[k] = slog[128 + lj];
            invc[k] = sinv[128 + lj];
            colp[k] = 0.f;
        }

#pragma unroll
        for (int mi = 0; mi < 2; mi++) {
#pragma unroll
            for (int h = 0; h < 2; h++) {
                const int li = wm * 32 + mi * 16 + h * 8 + g;
                const int gi = I * 128 + li;
                const float logr = slog[li];
                const float invr = sinv[li];
                float rsum = 0.f;
#pragma unroll
                for (int ni = 0; ni < 8; ni++) {
                    // pair exp via ex2.f16x2
                    float x0 = fmaf(acc[mi][ni][h * 2 + 0], C2A, -C2B);
                    float x1 = fmaf(acc[mi][ni][h * 2 + 1], C2A, -C2B);
                    __half2 hx = __floats2half2_rn(x0, x1);
                    uint32_t xu = *reinterpret_cast<uint32_t*>(&hx), eu;
                    asm("ex2.approx.f16x2 %0, %1;" : "=r"(eu) : "r"(xu));
                    __half2 he = *reinterpret_cast<__half2*>(&eu);
                    float2 fe = __half22float2(he);
#pragma unroll
                    for (int e = 0; e < 2; e++) {
                        const int k = ni * 2 + e;
                        float el = (e == 0) ? fe.x : fe.y;
                        float l = fmaf(acc[mi][ni][h * 2 + e], RSC, -2.0f);
                        if (!diag) {
                            float qc = el * invc[k];
                            colp[k] += (l - logc[k]) - qc * fmaf(qc, -0.5f, 1.0f);
                        }
                        int gj = J * 128 + wn * 64 + ni * 8 + tig * 2 + e;
                        if (!diag || gi != gj) {
                            float qr = el * invr;
                            rsum += (l - logr) - qr * fmaf(qr, -0.5f, 1.0f);
                        }
                    }
                }
                rsum += __shfl_xor_sync(0xffffffffu, rsum, 1);
                rsum += __shfl_xor_sync(0xffffffffu, rsum, 2);
                if (tig == 0) atomicAdd(&g_pos_sum[gi], rsum);
            }
        }

        if (!diag) {
#pragma unroll
            for (int k = 0; k < 16; k++) {
                float v = colp[k];
                v += __shfl_xor_sync(0xffffffffu, v, 4);
                v += __shfl_xor_sync(0xffffffffu, v, 8);
                v += __shfl_xor_sync(0xffffffffu, v, 16);
                if (lane < 4) {
                    int gj = J * 128 + wn * 64 + (k >> 1) * 8 + lane * 2 + (k & 1);
                    atomicAdd(&g_pos_sum[gj], v);
                }
            }
        }
        __syncthreads();                         // table reuse fence
    }
}

// ---------------------------------------------------------------------------
// K4: loss = -mean_i( pos_sum[i] / (V * same_label_count(t_i) - 1) )
// ---------------------------------------------------------------------------
__global__ void k_final(const int* __restrict__ labels, float* __restrict__ out) {
    __shared__ float rcnt[TT];
    __shared__ float wred[8];
    const int tid = threadIdx.x;
    if (tid < TT) {
        int ml = labels[tid], c = 0;
        for (int u = 0; u < TT; u++) c += (labels[u] == ml) ? 1 : 0;
        rcnt[tid] = 1.0f / (float)(c * VV - 1);   // always >= 255 > EPS
    }
    __syncthreads();
    const int i = blockIdx.x * 256 + tid;         // 32*256 == MTOT
    float s = g_pos_sum[i] * rcnt[i >> 8];
#pragma unroll
    for (int off = 16; off > 0; off >>= 1)
        s += __shfl_xor_sync(0xffffffffu, s, off);
    if ((tid & 31) == 0) wred[tid >> 5] = s;
    __syncthreads();
    if (tid == 0) {
        float t = 0.f;
#pragma unroll
        for (int w = 0; w < 8; w++) t += wred[w];
        atomicAdd(out, -t * (1.0f / (float)MTOT));
    }
}

// ---------------------------------------------------------------------------
extern "C" void kernel_launch(void* const* d_in, const int* in_sizes, int n_in,
                              void* d_out, int out_size) {
    const float* features   = (const float*)d_in[0];
    const int*   batch_inds = (const int*)d_in[1];
    const int*   si32       = (const int*)d_in[2];  // int32 or int64 (sniffed)
    const int*   labels     = (const int*)d_in[3];
    float*       out        = (float*)d_out;

    cudaFuncSetAttribute(k_neg, cudaFuncAttributeMaxDynamicSharedMemorySize, SMEM_MAIN);
    cudaFuncSetAttribute(k_pos, cudaFuncAttributeMaxDynamicSharedMemorySize, SMEM_MAIN);

    k_gather<<<dim3(4, TT), 256>>>(features, batch_inds, si32, labels, out);
    k_neg<<<152, 256, SMEM_MAIN>>>();
    k_pos<<<152, 256, SMEM_MAIN>>>();
    k_final<<<32, 256>>>(labels, out);
}